// round 13
// baseline (speedup 1.0000x reference)
#include <cuda_runtime.h>
#include <cuda_bf16.h>
#include <cstdint>

#define N_NODES 100000
#define N_EDGES 1600000
#define IN_DIM 128
#define EDGE_DIM 64
#define HD 64
#define OUT_DIM 8
#define TILE_E 64
#define QKV_NODES 16
#define PITCH_A 68          // sea row pitch (uint32 words)

// ---------------- scratch ----------------------------------------------------
__device__ float g_Q[(size_t)N_NODES * HD];
__device__ float g_K[(size_t)N_NODES * HD];
__device__ float g_VWT[(size_t)N_NODES * HD];  // (V @ Wo) transposed: [n][j][h]
__device__ float g_sum[(size_t)N_NODES * OUT_DIM];
__device__ int   g_cnt[N_NODES];
__device__ int   g_i64flag;

__device__ __forceinline__ uint32_t f2tf32(float f) {
    uint32_t r;
    asm("cvt.rna.tf32.f32 %0, %1;" : "=r"(r) : "f"(f));
    return r;
}
__device__ __forceinline__ void mma_tf32(
    float& d0, float& d1, float& d2, float& d3,
    uint32_t a0, uint32_t a1, uint32_t a2, uint32_t a3,
    uint32_t b0, uint32_t b1)
{
    asm("mma.sync.aligned.m16n8k8.row.col.f32.tf32.tf32.f32 "
        "{%0,%1,%2,%3}, {%4,%5,%6,%7}, {%8,%9}, {%0,%1,%2,%3};"
        : "+f"(d0), "+f"(d1), "+f"(d2), "+f"(d3)
        : "r"(a0), "r"(a1), "r"(a2), "r"(a3), "r"(b0), "r"(b1));
}

__global__ void zero_kernel() {
    int i = blockIdx.x * blockDim.x + threadIdx.x;
    if (i < N_NODES * OUT_DIM) g_sum[i] = 0.f;
    if (i < N_NODES) g_cnt[i] = 0;
}

__global__ void detect_kernel(const void* ei) {
    if (threadIdx.x == 0 && blockIdx.x == 0) {
        const unsigned long long* p = (const unsigned long long*)ei;
        int is64 = 1;
        for (int i = 0; i < 64; i++)
            if (p[i] >= (unsigned long long)N_NODES) { is64 = 0; break; }
        g_i64flag = is64;
    }
}

// ---------------- QKV projection + fused VWT = (V @ Wo)^T per node -----------
__global__ __launch_bounds__(192) void qkv_kernel(
    const float* __restrict__ x,
    const float* __restrict__ Wq, const float* __restrict__ bq,
    const float* __restrict__ Wk, const float* __restrict__ bk,
    const float* __restrict__ Wv, const float* __restrict__ bv,
    const float* __restrict__ Wo)
{
    __shared__ float xs[QKV_NODES][IN_DIM];
    __shared__ float xv[QKV_NODES][HD + 1];
    __shared__ float swo[HD * 9];
    const int nb = blockIdx.x * QKV_NODES;
    const int t = threadIdx.x;

    for (int i = t; i < HD * OUT_DIM; i += 192) swo[(i >> 3) * 9 + (i & 7)] = Wo[i];
    for (int i = t; i < QKV_NODES * (IN_DIM / 4); i += 192) {
        int n = i >> 5, kk = i & 31;
        *(float4*)&xs[n][kk * 4] =
            *(const float4*)&x[(size_t)(nb + n) * IN_DIM + kk * 4];
    }
    __syncthreads();

    const int m = t >> 6, c = t & 63;
    const float* W = (m == 0) ? Wq : (m == 1) ? Wk : Wv;
    const float* b = (m == 0) ? bq : (m == 1) ? bk : bv;

    float acc[QKV_NODES];
#pragma unroll
    for (int n = 0; n < QKV_NODES; n++) acc[n] = 0.f;

#pragma unroll 2
    for (int k = 0; k < IN_DIM; k += 4) {
        float w0 = W[(k + 0) * HD + c];
        float w1 = W[(k + 1) * HD + c];
        float w2 = W[(k + 2) * HD + c];
        float w3 = W[(k + 3) * HD + c];
#pragma unroll
        for (int n = 0; n < QKV_NODES; n++) {
            float4 xvv = *(const float4*)&xs[n][k];
            acc[n] = fmaf(xvv.x, w0, fmaf(xvv.y, w1,
                     fmaf(xvv.z, w2, fmaf(xvv.w, w3, acc[n]))));
        }
    }
    const float bc = b[c];
    if (m == 2) {
#pragma unroll
        for (int n = 0; n < QKV_NODES; n++) xv[n][c] = acc[n] + bc;
    } else {
        float* dstp = (m == 0) ? g_Q : g_K;
#pragma unroll
        for (int n = 0; n < QKV_NODES; n++)
            dstp[(size_t)(nb + n) * HD + c] = acc[n] + bc;
    }
    __syncthreads();

    // VWT[n][j*8+h] = sum_d V[n][h*8+d] * Wo[h*8+d][j]
    for (int i = t; i < QKV_NODES * HD; i += 192) {
        int n = i >> 6, cc = i & 63;
        int h = cc >> 3, j = cc & 7;
        const float* vr = &xv[n][h << 3];
        const float* wr = &swo[(h << 3) * 9 + j];
        float s = 0.f;
#pragma unroll
        for (int d = 0; d < 8; d++) s = fmaf(vr[d], wr[d * 9], s);
        g_VWT[(size_t)(nb + n) * HD + j * 8 + h] = s;
    }
}

// ---------------- per-edge kernel --------------------------------------------
// 128 threads, tile = 64 edges. 6 CTAs/SM target (regs<=85, smem ~35.5KB).
__global__ __launch_bounds__(128, 6) void edge_kernel(
    const float* __restrict__ edge_attr,
    const float* __restrict__ We, const float* __restrict__ be,
    const void* __restrict__ ei)
{
    __shared__ uint2    sBf[64 * 32];          // B fragments: [(h*8+q)][lane], 16KB
    __shared__ uint32_t sea[TILE_E * PITCH_A]; // A tile (tf32), 17.4KB
    __shared__ float    sscw[TILE_E * 9];      // scores, then (aliased) weights
    __shared__ float    sbe[HD];

    const int t = threadIdx.x;
    const int lane = t & 31;
    const int g = lane >> 2;
    const int c = lane & 3;
    const int wbase = (t >> 5) * 16;
    const int h = t & 7;
    const int eg = t >> 3;
    const int ebase = eg * 4;
    const int is64 = g_i64flag;

    // pack We into mma B-fragment order (tf32), once per block
    for (int i = t; i < 64 * 32; i += 128) {
        int hq = i >> 5, ln = i & 31;
        int hh = hq >> 3, q = hq & 7;
        int gg = ln >> 2, cc = ln & 3;
        float w0 = We[(8 * q + cc) * HD + 8 * hh + gg];
        float w1 = We[(8 * q + cc + 4) * HD + 8 * hh + gg];
        sBf[i] = make_uint2(f2tf32(w0), f2tf32(w1));
    }
    if (t < HD) sbe[t] = be[t];
    __syncthreads();

    const float inv_sqrt_d = 0.35355339059327373f;
    const int ntiles = N_EDGES / TILE_E;
    for (int tile = blockIdx.x; tile < ntiles; tile += gridDim.x) {
        const int e0 = tile * TILE_E;

        int src[4], dst[4];
        if (is64) {
            const longlong2* ps = (const longlong2*)((const long long*)ei + (e0 + ebase));
            const longlong2* pd = (const longlong2*)((const long long*)ei + N_EDGES + (e0 + ebase));
            longlong2 s01 = ps[0], s23 = ps[1], d01 = pd[0], d23 = pd[1];
            src[0] = (int)s01.x; src[1] = (int)s01.y; src[2] = (int)s23.x; src[3] = (int)s23.y;
            dst[0] = (int)d01.x; dst[1] = (int)d01.y; dst[2] = (int)d23.x; dst[3] = (int)d23.y;
        } else {
            int4 s = *(const int4*)((const int*)ei + (e0 + ebase));
            int4 d = *(const int4*)((const int*)ei + N_EDGES + (e0 + ebase));
            src[0] = s.x; src[1] = s.y; src[2] = s.z; src[3] = s.w;
            dst[0] = d.x; dst[1] = d.y; dst[2] = d.z; dst[3] = d.w;
        }

        // stage edge_attr tile, tf32-converted
        for (int i = t; i < TILE_E * 16; i += 128) {
            int e = i >> 4, k4 = i & 15;
            float4 v = *(const float4*)&edge_attr[(size_t)(e0 + e) * EDGE_DIM + k4 * 4];
            uint32_t* dstw = &sea[e * PITCH_A + k4 * 4];
            dstw[0] = f2tf32(v.x);
            dstw[1] = f2tf32(v.y);
            dstw[2] = f2tf32(v.z);
            dstw[3] = f2tf32(v.w);
        }

        // Q/K gathers + fold, 2 edges at a time (32 live regs max)
#pragma unroll
        for (int b = 0; b < 2; b++) {
            float4 qa0, qa1, ka0, ka1, qb0, qb1, kb0, kb1;
            {
                const float4* qp = (const float4*)(g_Q + (size_t)src[2 * b] * HD + h * 8);
                const float4* kp = (const float4*)(g_K + (size_t)dst[2 * b] * HD + h * 8);
                qa0 = qp[0]; qa1 = qp[1]; ka0 = kp[0]; ka1 = kp[1];
            }
            {
                const float4* qp = (const float4*)(g_Q + (size_t)src[2 * b + 1] * HD + h * 8);
                const float4* kp = (const float4*)(g_K + (size_t)dst[2 * b + 1] * HD + h * 8);
                qb0 = qp[0]; qb1 = qp[1]; kb0 = kp[0]; kb1 = kp[1];
            }
            float qk0 = qa0.x * ka0.x + qa0.y * ka0.y + qa0.z * ka0.z + qa0.w * ka0.w
                      + qa1.x * ka1.x + qa1.y * ka1.y + qa1.z * ka1.z + qa1.w * ka1.w;
            float qk1 = qb0.x * kb0.x + qb0.y * kb0.y + qb0.z * kb0.z + qb0.w * kb0.w
                      + qb1.x * kb1.x + qb1.y * kb1.y + qb1.z * kb1.z + qb1.w * kb1.w;
            sscw[(ebase + 2 * b) * 9 + h] = qk0;
            sscw[(ebase + 2 * b + 1) * 9 + h] = qk1;
        }
        __syncthreads();

        // ---- mma phase ----
        uint32_t afr[8][4];
#pragma unroll
        for (int q = 0; q < 8; q++) {
            const uint32_t* r0 = &sea[(wbase + g) * PITCH_A + 8 * q];
            const uint32_t* r1 = &sea[(wbase + g + 8) * PITCH_A + 8 * q];
            afr[q][0] = r0[c];
            afr[q][1] = r1[c];
            afr[q][2] = r0[c + 4];
            afr[q][3] = r1[c + 4];
        }

#pragma unroll
        for (int hh = 0; hh < 8; hh++) {
            float d0 = 0.f, d1 = 0.f, d2 = 0.f, d3 = 0.f;
#pragma unroll
            for (int q = 0; q < 8; q++) {
                uint2 b = sBf[(hh * 8 + q) * 32 + lane];
                mma_tf32(d0, d1, d2, d3,
                         afr[q][0], afr[q][1], afr[q][2], afr[q][3], b.x, b.y);
            }
            float2 bev = *(const float2*)&sbe[8 * hh + 2 * c];
            float e00 = d0 + bev.x, e01 = d1 + bev.y;
            float e10 = d2 + bev.x, e11 = d3 + bev.y;
            float p0 = e00 * e00 + e01 * e01;   // edge wbase+g
            float p1 = e10 * e10 + e11 * e11;   // edge wbase+g+8
            p0 += __shfl_xor_sync(0xffffffffu, p0, 1);
            p0 += __shfl_xor_sync(0xffffffffu, p0, 2);
            p1 += __shfl_xor_sync(0xffffffffu, p1, 1);
            p1 += __shfl_xor_sync(0xffffffffu, p1, 2);
            if (c == 0) {
                sscw[(wbase + g) * 9 + hh] += p0;
                sscw[(wbase + g + 8) * 9 + hh] += p1;
            }
        }
        __syncthreads();

        // ---- phase A: softmax per edge (2 threads/edge), weights in place ----
        {
            int e = t >> 1;
            int hb = (t & 1) * 4;
            float* sp = &sscw[e * 9 + hb];
            float s0 = sp[0] * inv_sqrt_d;
            float s1 = sp[1] * inv_sqrt_d;
            float s2 = sp[2] * inv_sqrt_d;
            float s3 = sp[3] * inv_sqrt_d;
            float mx = fmaxf(fmaxf(s0, s1), fmaxf(s2, s3));
            mx = fmaxf(mx, __shfl_xor_sync(0xffffffffu, mx, 1));
            float x0 = __expf(s0 - mx);
            float x1 = __expf(s1 - mx);
            float x2 = __expf(s2 - mx);
            float x3 = __expf(s3 - mx);
            float sm = (x0 + x1) + (x2 + x3);
            sm += __shfl_xor_sync(0xffffffffu, sm, 1);
            float inv = __fdividef(1.0f, sm);
            sp[0] = x0 * inv;
            sp[1] = x1 * inv;
            sp[2] = x2 * inv;
            sp[3] = x3 * inv;
        }
        __syncthreads();

        // ---- phase B: thread (eg, j): out[e][j] = dot(wgt[e], VWT[dst][j]) ----
        const int j = h;
        {
            const float4* vp0 = (const float4*)(g_VWT + (size_t)dst[0] * HD + j * 8);
            float4 a0c = vp0[0], a1c = vp0[1];
#pragma unroll
            for (int i = 0; i < 4; i++) {
                float4 a0n, a1n;
                if (i < 3) {
                    const float4* vpn = (const float4*)(g_VWT + (size_t)dst[i + 1] * HD + j * 8);
                    a0n = vpn[0]; a1n = vpn[1];
                }
                const float* wp = &sscw[(ebase + i) * 9];
                float res = wp[0] * a0c.x + wp[1] * a0c.y
                          + wp[2] * a0c.z + wp[3] * a0c.w
                          + wp[4] * a1c.x + wp[5] * a1c.y
                          + wp[6] * a1c.z + wp[7] * a1c.w;
                atomicAdd(&g_sum[(size_t)src[i] * OUT_DIM + j], res);
                if (i < 3) { a0c = a0n; a1c = a1n; }
            }
        }
        if (j == 0) {
#pragma unroll
            for (int i = 0; i < 4; i++) atomicAdd(&g_cnt[src[i]], 1);
        }
        __syncthreads();   // sscw / sea reused next tile
    }
}

__global__ void finalize_kernel(float* __restrict__ out, const float* __restrict__ bo) {
    int i = blockIdx.x * blockDim.x + threadIdx.x;
    if (i < N_NODES * OUT_DIM) {
        int n = i >> 3, j = i & 7;
        int c = g_cnt[n];
        float r = 0.f;
        if (c > 0) r = g_sum[i] / (float)c + bo[j];
        out[i] = r;
    }
}

extern "C" void kernel_launch(void* const* d_in, const int* in_sizes, int n_in,
                              void* d_out, int out_size)
{
    const float* x  = (const float*)d_in[0];
    const float* ea = (const float*)d_in[1];
    const float* Wq = (const float*)d_in[2];
    const float* bq = (const float*)d_in[3];
    const float* Wk = (const float*)d_in[4];
    const float* bk = (const float*)d_in[5];
    const float* Wv = (const float*)d_in[6];
    const float* bv = (const float*)d_in[7];
    const float* We = (const float*)d_in[8];
    const float* be = (const float*)d_in[9];
    const float* Wo = (const float*)d_in[10];
    const float* bo = (const float*)d_in[11];
    const void*  ei = d_in[12];
    float* out = (float*)d_out;

    zero_kernel<<<(N_NODES * OUT_DIM + 255) / 256, 256>>>();
    detect_kernel<<<1, 32>>>(ei);
    qkv_kernel<<<N_NODES / QKV_NODES, 192>>>(x, Wq, bq, Wk, bk, Wv, bv, Wo);
    edge_kernel<<<888, 128>>>(ea, We, be, ei);
    finalize_kernel<<<(N_NODES * OUT_DIM + 255) / 256, 256>>>(out, bo);
}

// round 15
// speedup vs baseline: 1.1727x; 1.1727x over previous
#include <cuda_runtime.h>
#include <cuda_bf16.h>
#include <cstdint>

#define N_NODES 100000
#define N_EDGES 1600000
#define IN_DIM 128
#define EDGE_DIM 64
#define HD 64
#define OUT_DIM 8
#define TILE_E 64
#define PITCH_A 68          // edge A-tile row pitch (uint32 words, 64-wide rows)
#define PITCH_X 132         // x-tile row pitch (uint32 words, 128-wide rows)

// ---------------- scratch ----------------------------------------------------
__device__ float g_Q[(size_t)N_NODES * HD];
__device__ float g_K[(size_t)N_NODES * HD];
__device__ float g_VWT[(size_t)N_NODES * HD];  // (V @ Wo) transposed: [n][j][h]
__device__ float g_sum[(size_t)N_NODES * OUT_DIM];
__device__ int   g_cnt[N_NODES];
__device__ int   g_i64flag;

__device__ __forceinline__ uint32_t f2tf32(float f) {
    uint32_t r;
    asm("cvt.rna.tf32.f32 %0, %1;" : "=r"(r) : "f"(f));
    return r;
}
__device__ __forceinline__ void mma_tf32(
    float& d0, float& d1, float& d2, float& d3,
    uint32_t a0, uint32_t a1, uint32_t a2, uint32_t a3,
    uint32_t b0, uint32_t b1)
{
    asm("mma.sync.aligned.m16n8k8.row.col.f32.tf32.tf32.f32 "
        "{%0,%1,%2,%3}, {%4,%5,%6,%7}, {%8,%9}, {%0,%1,%2,%3};"
        : "+f"(d0), "+f"(d1), "+f"(d2), "+f"(d3)
        : "r"(a0), "r"(a1), "r"(a2), "r"(a3), "r"(b0), "r"(b1));
}

__global__ void zero_kernel() {
    int i = blockIdx.x * blockDim.x + threadIdx.x;
    if (i < N_NODES * OUT_DIM) g_sum[i] = 0.f;
    if (i < N_NODES) g_cnt[i] = 0;
}

__global__ void detect_kernel(const void* ei) {
    if (threadIdx.x == 0 && blockIdx.x == 0) {
        const unsigned long long* p = (const unsigned long long*)ei;
        int is64 = 1;
        for (int i = 0; i < 64; i++)
            if (p[i] >= (unsigned long long)N_NODES) { is64 = 0; break; }
        g_i64flag = is64;
    }
}

// ---------------- Q/K projections via tf32 mma --------------------------------
// grid (N_NODES/16, 2): 16 nodes per block; blockIdx.y selects Q or K.
// 4 warps; warp w computes column-tiles 2w, 2w+1 (16 cols) of the 16x64 output.
__global__ __launch_bounds__(128) void qk_kernel(
    const float* __restrict__ x,
    const float* __restrict__ Wq, const float* __restrict__ bq,
    const float* __restrict__ Wk, const float* __restrict__ bk)
{
    __shared__ uint2    sWf[16 * 8 * 32];   // W fragments [(q*8+nt)][lane], 32KB
    __shared__ uint32_t sxa[16 * PITCH_X];  // x tile (tf32), 8.4KB

    const int t = threadIdx.x;
    const int lane = t & 31;
    const int warp = t >> 5;
    const int g = lane >> 2;
    const int c = lane & 3;
    const int nb = blockIdx.x * 16;
    const int m = blockIdx.y;
    const float* W = (m == 0) ? Wq : Wk;
    const float* b = (m == 0) ? bq : bk;
    float* D = (m == 0) ? g_Q : g_K;

    // pack W into mma B-fragment order (tf32): col-tile nt, k-step q
    for (int i = t; i < 16 * 8 * 32; i += 128) {
        int q = i >> 8;
        int nt = (i >> 5) & 7;
        int ln = i & 31;
        int gg = ln >> 2, cc = ln & 3;
        float w0 = W[(8 * q + cc) * HD + 8 * nt + gg];
        float w1 = W[(8 * q + cc + 4) * HD + 8 * nt + gg];
        sWf[i] = make_uint2(f2tf32(w0), f2tf32(w1));
    }
    // stage x tile (16 nodes x 128 k), tf32-converted
    for (int i = t; i < 16 * 32; i += 128) {
        int n = i >> 5, k4 = i & 31;
        float4 v = *(const float4*)&x[(size_t)(nb + n) * IN_DIM + k4 * 4];
        uint32_t* d = &sxa[n * PITCH_X + k4 * 4];
        d[0] = f2tf32(v.x); d[1] = f2tf32(v.y);
        d[2] = f2tf32(v.z); d[3] = f2tf32(v.w);
    }
    __syncthreads();

    const int ntb = warp * 2;
    float acc[2][4];
#pragma unroll
    for (int nt = 0; nt < 2; nt++)
#pragma unroll
        for (int r = 0; r < 4; r++) acc[nt][r] = 0.f;

#pragma unroll
    for (int q = 0; q < 16; q++) {
        const uint32_t* r0 = &sxa[g * PITCH_X + 8 * q];
        const uint32_t* r1 = &sxa[(g + 8) * PITCH_X + 8 * q];
        uint32_t a0 = r0[c], a1 = r1[c], a2 = r0[c + 4], a3 = r1[c + 4];
#pragma unroll
        for (int nt = 0; nt < 2; nt++) {
            uint2 bf = sWf[(q * 8 + ntb + nt) * 32 + lane];
            mma_tf32(acc[nt][0], acc[nt][1], acc[nt][2], acc[nt][3],
                     a0, a1, a2, a3, bf.x, bf.y);
        }
    }

#pragma unroll
    for (int nt = 0; nt < 2; nt++) {
        int col = (ntb + nt) * 8 + 2 * c;
        float2 bv = *(const float2*)&b[col];
        int row0 = nb + g;
        float2 o0 = make_float2(acc[nt][0] + bv.x, acc[nt][1] + bv.y);
        float2 o1 = make_float2(acc[nt][2] + bv.x, acc[nt][3] + bv.y);
        *(float2*)&D[(size_t)row0 * HD + col] = o0;
        *(float2*)&D[(size_t)(row0 + 8) * HD + col] = o1;
    }
}

// ---------------- V projection (fp32) + fused VWT = (V @ Wo)^T -----------------
// 32 nodes/block, 128 threads: c = t&63 column, half = t>>6 selects 16 nodes.
__global__ __launch_bounds__(128) void v_kernel(
    const float* __restrict__ x,
    const float* __restrict__ Wv, const float* __restrict__ bv,
    const float* __restrict__ Wo)
{
    __shared__ float xs[32][IN_DIM];    // 16KB
    __shared__ float xv[32][HD + 1];    // 8.3KB
    __shared__ float swo[HD * 9];       // 2.3KB
    const int nb = blockIdx.x * 32;
    const int t = threadIdx.x;

    for (int i = t; i < HD * OUT_DIM; i += 128) swo[(i >> 3) * 9 + (i & 7)] = Wo[i];
    for (int i = t; i < 32 * (IN_DIM / 4); i += 128) {
        int n = i >> 5, kk = i & 31;
        *(float4*)&xs[n][kk * 4] =
            *(const float4*)&x[(size_t)(nb + n) * IN_DIM + kk * 4];
    }
    __syncthreads();

    const int c = t & 63, half = t >> 6;
    const int nbase = half * 16;

    float acc[16];
#pragma unroll
    for (int n = 0; n < 16; n++) acc[n] = 0.f;

#pragma unroll 2
    for (int k = 0; k < IN_DIM; k += 4) {
        float w0 = Wv[(k + 0) * HD + c];
        float w1 = Wv[(k + 1) * HD + c];
        float w2 = Wv[(k + 2) * HD + c];
        float w3 = Wv[(k + 3) * HD + c];
#pragma unroll
        for (int n = 0; n < 16; n++) {
            float4 xvv = *(const float4*)&xs[nbase + n][k];
            acc[n] = fmaf(xvv.x, w0, fmaf(xvv.y, w1,
                     fmaf(xvv.z, w2, fmaf(xvv.w, w3, acc[n]))));
        }
    }
    const float bc = bv[c];
#pragma unroll
    for (int n = 0; n < 16; n++) xv[nbase + n][c] = acc[n] + bc;
    __syncthreads();

    // VWT[n][j*8+h] = sum_d V[n][h*8+d] * Wo[h*8+d][j]
    for (int i = t; i < 32 * HD; i += 128) {
        int n = i >> 6, cc = i & 63;
        int h = cc >> 3, j = cc & 7;
        const float* vr = &xv[n][h << 3];
        const float* wr = &swo[(h << 3) * 9 + j];
        float s = 0.f;
#pragma unroll
        for (int d = 0; d < 8; d++) s = fmaf(vr[d], wr[d * 9], s);
        g_VWT[(size_t)(nb + n) * HD + j * 8 + h] = s;
    }
}

// ---------------- per-edge kernel (proven R12 configuration) -------------------
__global__ __launch_bounds__(128) void edge_kernel(
    const float* __restrict__ edge_attr,
    const float* __restrict__ We, const float* __restrict__ be,
    const void* __restrict__ ei)
{
    __shared__ uint2    sBf[64 * 32];          // B fragments: [(h*8+q)][lane]
    __shared__ uint32_t sea[TILE_E * PITCH_A]; // A tile (tf32)
    __shared__ float    ssc[TILE_E * 9];       // scores: qk + sum((E+be)^2)
    __shared__ float    swt[TILE_E * 9];       // softmax weights
    __shared__ float    sbe[HD];

    const int t = threadIdx.x;
    const int lane = t & 31;
    const int g = lane >> 2;
    const int c = lane & 3;
    const int wbase = (t >> 5) * 16;
    const int h = t & 7;
    const int eg = t >> 3;
    const int ebase = eg * 4;
    const int is64 = g_i64flag;

    for (int i = t; i < 64 * 32; i += 128) {
        int hq = i >> 5, ln = i & 31;
        int hh = hq >> 3, q = hq & 7;
        int gg = ln >> 2, cc = ln & 3;
        float w0 = We[(8 * q + cc) * HD + 8 * hh + gg];
        float w1 = We[(8 * q + cc + 4) * HD + 8 * hh + gg];
        sBf[i] = make_uint2(f2tf32(w0), f2tf32(w1));
    }
    if (t < HD) sbe[t] = be[t];
    __syncthreads();

    const float inv_sqrt_d = 0.35355339059327373f;
    const int ntiles = N_EDGES / TILE_E;
    for (int tile = blockIdx.x; tile < ntiles; tile += gridDim.x) {
        const int e0 = tile * TILE_E;

        int src[4], dst[4];
        if (is64) {
            const longlong2* ps = (const longlong2*)((const long long*)ei + (e0 + ebase));
            const longlong2* pd = (const longlong2*)((const long long*)ei + N_EDGES + (e0 + ebase));
            longlong2 s01 = ps[0], s23 = ps[1], d01 = pd[0], d23 = pd[1];
            src[0] = (int)s01.x; src[1] = (int)s01.y; src[2] = (int)s23.x; src[3] = (int)s23.y;
            dst[0] = (int)d01.x; dst[1] = (int)d01.y; dst[2] = (int)d23.x; dst[3] = (int)d23.y;
        } else {
            int4 s = *(const int4*)((const int*)ei + (e0 + ebase));
            int4 d = *(const int4*)((const int*)ei + N_EDGES + (e0 + ebase));
            src[0] = s.x; src[1] = s.y; src[2] = s.z; src[3] = s.w;
            dst[0] = d.x; dst[1] = d.y; dst[2] = d.z; dst[3] = d.w;
        }

        // Q/K gathers (L2-resident), all issued up front
        float4 q0[4], q1[4], k0[4], k1[4];
#pragma unroll
        for (int i = 0; i < 4; i++) {
            const float4* qp = (const float4*)(g_Q + (size_t)src[i] * HD + h * 8);
            const float4* kp = (const float4*)(g_K + (size_t)dst[i] * HD + h * 8);
            q0[i] = qp[0]; q1[i] = qp[1];
            k0[i] = kp[0]; k1[i] = kp[1];
        }

        // stage edge_attr tile, tf32-converted
        for (int i = t; i < TILE_E * 16; i += 128) {
            int e = i >> 4, k4 = i & 15;
            float4 v = *(const float4*)&edge_attr[(size_t)(e0 + e) * EDGE_DIM + k4 * 4];
            uint32_t* dstw = &sea[e * PITCH_A + k4 * 4];
            dstw[0] = f2tf32(v.x);
            dstw[1] = f2tf32(v.y);
            dstw[2] = f2tf32(v.z);
            dstw[3] = f2tf32(v.w);
        }

        // fold qk and park in ssc
#pragma unroll
        for (int i = 0; i < 4; i++) {
            float qk = q0[i].x * k0[i].x + q0[i].y * k0[i].y
                     + q0[i].z * k0[i].z + q0[i].w * k0[i].w
                     + q1[i].x * k1[i].x + q1[i].y * k1[i].y
                     + q1[i].z * k1[i].z + q1[i].w * k1[i].w;
            ssc[(ebase + i) * 9 + h] = qk;
        }
        __syncthreads();

        // ---- mma phase ----
        uint32_t afr[8][4];
#pragma unroll
        for (int q = 0; q < 8; q++) {
            const uint32_t* r0 = &sea[(wbase + g) * PITCH_A + 8 * q];
            const uint32_t* r1 = &sea[(wbase + g + 8) * PITCH_A + 8 * q];
            afr[q][0] = r0[c];
            afr[q][1] = r1[c];
            afr[q][2] = r0[c + 4];
            afr[q][3] = r1[c + 4];
        }

#pragma unroll
        for (int hh = 0; hh < 8; hh++) {
            float d0 = 0.f, d1 = 0.f, d2 = 0.f, d3 = 0.f;
#pragma unroll
            for (int q = 0; q < 8; q++) {
                uint2 b = sBf[(hh * 8 + q) * 32 + lane];
                mma_tf32(d0, d1, d2, d3,
                         afr[q][0], afr[q][1], afr[q][2], afr[q][3], b.x, b.y);
            }
            float2 bev = *(const float2*)&sbe[8 * hh + 2 * c];
            float e00 = d0 + bev.x, e01 = d1 + bev.y;
            float e10 = d2 + bev.x, e11 = d3 + bev.y;
            float p0 = e00 * e00 + e01 * e01;
            float p1 = e10 * e10 + e11 * e11;
            p0 += __shfl_xor_sync(0xffffffffu, p0, 1);
            p0 += __shfl_xor_sync(0xffffffffu, p0, 2);
            p1 += __shfl_xor_sync(0xffffffffu, p1, 1);
            p1 += __shfl_xor_sync(0xffffffffu, p1, 2);
            if (c == 0) {
                ssc[(wbase + g) * 9 + hh] += p0;
                ssc[(wbase + g + 8) * 9 + hh] += p1;
            }
        }
        __syncthreads();

        // ---- phase A: softmax per edge (2 threads/edge) ----
        {
            int e = t >> 1;
            int hb = (t & 1) * 4;
            const float* sp = &ssc[e * 9 + hb];
            float s0 = sp[0] * inv_sqrt_d;
            float s1 = sp[1] * inv_sqrt_d;
            float s2 = sp[2] * inv_sqrt_d;
            float s3 = sp[3] * inv_sqrt_d;
            float mx = fmaxf(fmaxf(s0, s1), fmaxf(s2, s3));
            mx = fmaxf(mx, __shfl_xor_sync(0xffffffffu, mx, 1));
            float x0 = __expf(s0 - mx);
            float x1 = __expf(s1 - mx);
            float x2 = __expf(s2 - mx);
            float x3 = __expf(s3 - mx);
            float sm = (x0 + x1) + (x2 + x3);
            sm += __shfl_xor_sync(0xffffffffu, sm, 1);
            float inv = __fdividef(1.0f, sm);
            float* wp = &swt[e * 9 + hb];
            wp[0] = x0 * inv;
            wp[1] = x1 * inv;
            wp[2] = x2 * inv;
            wp[3] = x3 * inv;
        }
        __syncthreads();

        // ---- phase B: thread (eg, j): out[e][j] = dot(wgt[e], VWT[dst][j]) ----
        const int j = h;
        float4 a0[4], a1[4];
#pragma unroll
        for (int i = 0; i < 4; i++) {
            const float4* vp = (const float4*)(g_VWT + (size_t)dst[i] * HD + j * 8);
            a0[i] = vp[0]; a1[i] = vp[1];
        }
#pragma unroll
        for (int i = 0; i < 4; i++) {
            const float* wp = &swt[(ebase + i) * 9];
            float res = wp[0] * a0[i].x + wp[1] * a0[i].y
                      + wp[2] * a0[i].z + wp[3] * a0[i].w
                      + wp[4] * a1[i].x + wp[5] * a1[i].y
                      + wp[6] * a1[i].z + wp[7] * a1[i].w;
            atomicAdd(&g_sum[(size_t)src[i] * OUT_DIM + j], res);
        }
        if (j == 0) {
#pragma unroll
            for (int i = 0; i < 4; i++) atomicAdd(&g_cnt[src[i]], 1);
        }
    }
}

__global__ void finalize_kernel(float* __restrict__ out, const float* __restrict__ bo) {
    int i = blockIdx.x * blockDim.x + threadIdx.x;
    if (i < N_NODES * OUT_DIM) {
        int n = i >> 3, j = i & 7;
        int c = g_cnt[n];
        float r = 0.f;
        if (c > 0) r = g_sum[i] / (float)c + bo[j];
        out[i] = r;
    }
}

extern "C" void kernel_launch(void* const* d_in, const int* in_sizes, int n_in,
                              void* d_out, int out_size)
{
    const float* x  = (const float*)d_in[0];
    const float* ea = (const float*)d_in[1];
    const float* Wq = (const float*)d_in[2];
    const float* bq = (const float*)d_in[3];
    const float* Wk = (const float*)d_in[4];
    const float* bk = (const float*)d_in[5];
    const float* Wv = (const float*)d_in[6];
    const float* bv = (const float*)d_in[7];
    const float* We = (const float*)d_in[8];
    const float* be = (const float*)d_in[9];
    const float* Wo = (const float*)d_in[10];
    const float* bo = (const float*)d_in[11];
    const void*  ei = d_in[12];
    float* out = (float*)d_out;

    zero_kernel<<<(N_NODES * OUT_DIM + 255) / 256, 256>>>();
    detect_kernel<<<1, 32>>>(ei);
    qk_kernel<<<dim3(N_NODES / 16, 2), 128>>>(x, Wq, bq, Wk, bk);
    v_kernel<<<N_NODES / 32, 128>>>(x, Wv, bv, Wo);
    edge_kernel<<<1184, 128>>>(ea, We, be, ei);
    finalize_kernel<<<(N_NODES * OUT_DIM + 255) / 256, 256>>>(out, bo);
}

// round 16
// speedup vs baseline: 1.3656x; 1.1645x over previous
#include <cuda_runtime.h>
#include <cuda_bf16.h>
#include <cstdint>

#define N_NODES 100000
#define N_EDGES 1600000
#define IN_DIM 128
#define EDGE_DIM 64
#define HD 64
#define OUT_DIM 8
#define TILE_E 64
#define PITCH_A 68          // edge A-tile row pitch (uint32 words)
#define PITCH_X 132         // x-tile row pitch (uint32 words)

// ---------------- scratch ----------------------------------------------------
__device__ float g_Q[(size_t)N_NODES * HD];
__device__ float g_K[(size_t)N_NODES * HD];
__device__ float g_VWT[(size_t)N_NODES * HD];  // (V @ Wo) transposed: [n][j][h]
__device__ float g_sum[(size_t)N_NODES * OUT_DIM];
__device__ int   g_cnt[N_NODES];
__device__ int   g_i64flag;

__device__ __forceinline__ uint32_t f2tf32(float f) {
    uint32_t r;
    asm("cvt.rna.tf32.f32 %0, %1;" : "=r"(r) : "f"(f));
    return r;
}
__device__ __forceinline__ void mma_tf32(
    float& d0, float& d1, float& d2, float& d3,
    uint32_t a0, uint32_t a1, uint32_t a2, uint32_t a3,
    uint32_t b0, uint32_t b1)
{
    asm("mma.sync.aligned.m16n8k8.row.col.f32.tf32.tf32.f32 "
        "{%0,%1,%2,%3}, {%4,%5,%6,%7}, {%8,%9}, {%0,%1,%2,%3};"
        : "+f"(d0), "+f"(d1), "+f"(d2), "+f"(d3)
        : "r"(a0), "r"(a1), "r"(a2), "r"(a3), "r"(b0), "r"(b1));
}

__global__ void zero_kernel() {
    int i = blockIdx.x * blockDim.x + threadIdx.x;
    if (i < N_NODES * OUT_DIM) g_sum[i] = 0.f;
    if (i < N_NODES) g_cnt[i] = 0;
}

__global__ void detect_kernel(const void* ei) {
    if (threadIdx.x == 0 && blockIdx.x == 0) {
        const unsigned long long* p = (const unsigned long long*)ei;
        int is64 = 1;
        for (int i = 0; i < 64; i++)
            if (p[i] >= (unsigned long long)N_NODES) { is64 = 0; break; }
        g_i64flag = is64;
    }
}

// ---------------- unified projections via tf32 mma ----------------------------
// grid (ceil(N/128), 3): 128 nodes per block in 8 x 16-node subtiles.
// blockIdx.y: 0 -> Q, 1 -> K, 2 -> V (stores VWT = (V@Wo)^T instead of V).
__global__ __launch_bounds__(128) void proj_kernel(
    const float* __restrict__ x,
    const float* __restrict__ Wq, const float* __restrict__ bq,
    const float* __restrict__ Wk, const float* __restrict__ bk,
    const float* __restrict__ Wv, const float* __restrict__ bv,
    const float* __restrict__ Wo)
{
    __shared__ uint2    sWf[16 * 8 * 32];   // W fragments [(q*8+nt)][lane], 32KB
    __shared__ uint32_t sxa[16 * PITCH_X];  // x subtile (tf32), 8.4KB
    __shared__ float    xv[16][65];         // V subtile (m==2 only), 4.2KB
    __shared__ float    swo[HD * 9];        // Wo (m==2 only), 2.3KB

    const int t = threadIdx.x;
    const int lane = t & 31;
    const int warp = t >> 5;
    const int g = lane >> 2;
    const int c = lane & 3;
    const int m = blockIdx.y;
    const float* W = (m == 0) ? Wq : (m == 1) ? Wk : Wv;
    const float* b = (m == 0) ? bq : (m == 1) ? bk : bv;

    // pack W into mma B-fragment order (tf32), once per block
    for (int i = t; i < 16 * 8 * 32; i += 128) {
        int q = i >> 8;
        int nt = (i >> 5) & 7;
        int ln = i & 31;
        int gg = ln >> 2, cc = ln & 3;
        float w0 = W[(8 * q + cc) * HD + 8 * nt + gg];
        float w1 = W[(8 * q + cc + 4) * HD + 8 * nt + gg];
        sWf[i] = make_uint2(f2tf32(w0), f2tf32(w1));
    }
    if (m == 2) {
        for (int i = t; i < HD * OUT_DIM; i += 128)
            swo[(i >> 3) * 9 + (i & 7)] = Wo[i];
    }
    __syncthreads();

    const int nb0 = blockIdx.x * 128;
    const int nsub = min(8, (N_NODES - nb0) >> 4);
    const int ntb = warp * 2;

    for (int sub = 0; sub < nsub; sub++) {
        const int nb = nb0 + sub * 16;

        // stage x subtile (16 nodes x 128 k), tf32-converted
        for (int i = t; i < 16 * 32; i += 128) {
            int n = i >> 5, k4 = i & 31;
            float4 v = *(const float4*)&x[(size_t)(nb + n) * IN_DIM + k4 * 4];
            uint32_t* d = &sxa[n * PITCH_X + k4 * 4];
            d[0] = f2tf32(v.x); d[1] = f2tf32(v.y);
            d[2] = f2tf32(v.z); d[3] = f2tf32(v.w);
        }
        __syncthreads();

        float acc[2][4];
#pragma unroll
        for (int nt = 0; nt < 2; nt++)
#pragma unroll
            for (int r = 0; r < 4; r++) acc[nt][r] = 0.f;

#pragma unroll
        for (int q = 0; q < 16; q++) {
            const uint32_t* r0 = &sxa[g * PITCH_X + 8 * q];
            const uint32_t* r1 = &sxa[(g + 8) * PITCH_X + 8 * q];
            uint32_t a0 = r0[c], a1 = r1[c], a2 = r0[c + 4], a3 = r1[c + 4];
#pragma unroll
            for (int nt = 0; nt < 2; nt++) {
                uint2 bf = sWf[(q * 8 + ntb + nt) * 32 + lane];
                mma_tf32(acc[nt][0], acc[nt][1], acc[nt][2], acc[nt][3],
                         a0, a1, a2, a3, bf.x, bf.y);
            }
        }

        if (m < 2) {
            float* D = (m == 0) ? g_Q : g_K;
#pragma unroll
            for (int nt = 0; nt < 2; nt++) {
                int col = (ntb + nt) * 8 + 2 * c;
                float2 bv2 = *(const float2*)&b[col];
                int row0 = nb + g;
                float2 o0 = make_float2(acc[nt][0] + bv2.x, acc[nt][1] + bv2.y);
                float2 o1 = make_float2(acc[nt][2] + bv2.x, acc[nt][3] + bv2.y);
                *(float2*)&D[(size_t)row0 * HD + col] = o0;
                *(float2*)&D[(size_t)(row0 + 8) * HD + col] = o1;
            }
            __syncthreads();   // protect sxa for next subtile
        } else {
            // park V (+bias) in smem, then compute VWT = (V @ Wo)^T
#pragma unroll
            for (int nt = 0; nt < 2; nt++) {
                int col = (ntb + nt) * 8 + 2 * c;
                float2 bv2 = *(const float2*)&b[col];
                xv[g][col]     = acc[nt][0] + bv2.x;
                xv[g][col + 1] = acc[nt][1] + bv2.y;
                xv[g + 8][col]     = acc[nt][2] + bv2.x;
                xv[g + 8][col + 1] = acc[nt][3] + bv2.y;
            }
            __syncthreads();
            for (int i = t; i < 16 * HD; i += 128) {
                int n = i >> 6, cc2 = i & 63;
                int h = cc2 >> 3, j = cc2 & 7;
                const float* vr = &xv[n][h << 3];
                const float* wr = &swo[(h << 3) * 9 + j];
                float s = 0.f;
#pragma unroll
                for (int d = 0; d < 8; d++) s = fmaf(vr[d], wr[d * 9], s);
                g_VWT[(size_t)(nb + n) * HD + j * 8 + h] = s;
            }
            __syncthreads();   // protect sxa + xv for next subtile
        }
    }
}

// ---------------- per-edge kernel (proven R12 configuration) -------------------
__global__ __launch_bounds__(128) void edge_kernel(
    const float* __restrict__ edge_attr,
    const float* __restrict__ We, const float* __restrict__ be,
    const void* __restrict__ ei)
{
    __shared__ uint2    sBf[64 * 32];          // B fragments: [(h*8+q)][lane]
    __shared__ uint32_t sea[TILE_E * PITCH_A]; // A tile (tf32)
    __shared__ float    ssc[TILE_E * 9];       // scores: qk + sum((E+be)^2)
    __shared__ float    swt[TILE_E * 9];       // softmax weights
    __shared__ float    sbe[HD];

    const int t = threadIdx.x;
    const int lane = t & 31;
    const int g = lane >> 2;
    const int c = lane & 3;
    const int wbase = (t >> 5) * 16;
    const int h = t & 7;
    const int eg = t >> 3;
    const int ebase = eg * 4;
    const int is64 = g_i64flag;

    for (int i = t; i < 64 * 32; i += 128) {
        int hq = i >> 5, ln = i & 31;
        int hh = hq >> 3, q = hq & 7;
        int gg = ln >> 2, cc = ln & 3;
        float w0 = We[(8 * q + cc) * HD + 8 * hh + gg];
        float w1 = We[(8 * q + cc + 4) * HD + 8 * hh + gg];
        sBf[i] = make_uint2(f2tf32(w0), f2tf32(w1));
    }
    if (t < HD) sbe[t] = be[t];
    __syncthreads();

    const float inv_sqrt_d = 0.35355339059327373f;
    const int ntiles = N_EDGES / TILE_E;
    for (int tile = blockIdx.x; tile < ntiles; tile += gridDim.x) {
        const int e0 = tile * TILE_E;

        int src[4], dst[4];
        if (is64) {
            const longlong2* ps = (const longlong2*)((const long long*)ei + (e0 + ebase));
            const longlong2* pd = (const longlong2*)((const long long*)ei + N_EDGES + (e0 + ebase));
            longlong2 s01 = ps[0], s23 = ps[1], d01 = pd[0], d23 = pd[1];
            src[0] = (int)s01.x; src[1] = (int)s01.y; src[2] = (int)s23.x; src[3] = (int)s23.y;
            dst[0] = (int)d01.x; dst[1] = (int)d01.y; dst[2] = (int)d23.x; dst[3] = (int)d23.y;
        } else {
            int4 s = *(const int4*)((const int*)ei + (e0 + ebase));
            int4 d = *(const int4*)((const int*)ei + N_EDGES + (e0 + ebase));
            src[0] = s.x; src[1] = s.y; src[2] = s.z; src[3] = s.w;
            dst[0] = d.x; dst[1] = d.y; dst[2] = d.z; dst[3] = d.w;
        }

        // Q/K gathers (L2-resident), all issued up front
        float4 q0[4], q1[4], k0[4], k1[4];
#pragma unroll
        for (int i = 0; i < 4; i++) {
            const float4* qp = (const float4*)(g_Q + (size_t)src[i] * HD + h * 8);
            const float4* kp = (const float4*)(g_K + (size_t)dst[i] * HD + h * 8);
            q0[i] = qp[0]; q1[i] = qp[1];
            k0[i] = kp[0]; k1[i] = kp[1];
        }

        // stage edge_attr tile, tf32-converted
        for (int i = t; i < TILE_E * 16; i += 128) {
            int e = i >> 4, k4 = i & 15;
            float4 v = *(const float4*)&edge_attr[(size_t)(e0 + e) * EDGE_DIM + k4 * 4];
            uint32_t* dstw = &sea[e * PITCH_A + k4 * 4];
            dstw[0] = f2tf32(v.x);
            dstw[1] = f2tf32(v.y);
            dstw[2] = f2tf32(v.z);
            dstw[3] = f2tf32(v.w);
        }

        // fold qk and park in ssc
#pragma unroll
        for (int i = 0; i < 4; i++) {
            float qk = q0[i].x * k0[i].x + q0[i].y * k0[i].y
                     + q0[i].z * k0[i].z + q0[i].w * k0[i].w
                     + q1[i].x * k1[i].x + q1[i].y * k1[i].y
                     + q1[i].z * k1[i].z + q1[i].w * k1[i].w;
            ssc[(ebase + i) * 9 + h] = qk;
        }
        __syncthreads();

        // ---- mma phase ----
        uint32_t afr[8][4];
#pragma unroll
        for (int q = 0; q < 8; q++) {
            const uint32_t* r0 = &sea[(wbase + g) * PITCH_A + 8 * q];
            const uint32_t* r1 = &sea[(wbase + g + 8) * PITCH_A + 8 * q];
            afr[q][0] = r0[c];
            afr[q][1] = r1[c];
            afr[q][2] = r0[c + 4];
            afr[q][3] = r1[c + 4];
        }

#pragma unroll
        for (int hh = 0; hh < 8; hh++) {
            float d0 = 0.f, d1 = 0.f, d2 = 0.f, d3 = 0.f;
#pragma unroll
            for (int q = 0; q < 8; q++) {
                uint2 b = sBf[(hh * 8 + q) * 32 + lane];
                mma_tf32(d0, d1, d2, d3,
                         afr[q][0], afr[q][1], afr[q][2], afr[q][3], b.x, b.y);
            }
            float2 bev = *(const float2*)&sbe[8 * hh + 2 * c];
            float e00 = d0 + bev.x, e01 = d1 + bev.y;
            float e10 = d2 + bev.x, e11 = d3 + bev.y;
            float p0 = e00 * e00 + e01 * e01;
            float p1 = e10 * e10 + e11 * e11;
            p0 += __shfl_xor_sync(0xffffffffu, p0, 1);
            p0 += __shfl_xor_sync(0xffffffffu, p0, 2);
            p1 += __shfl_xor_sync(0xffffffffu, p1, 1);
            p1 += __shfl_xor_sync(0xffffffffu, p1, 2);
            if (c == 0) {
                ssc[(wbase + g) * 9 + hh] += p0;
                ssc[(wbase + g + 8) * 9 + hh] += p1;
            }
        }
        __syncthreads();

        // ---- phase A: softmax per edge (2 threads/edge) ----
        {
            int e = t >> 1;
            int hb = (t & 1) * 4;
            const float* sp = &ssc[e * 9 + hb];
            float s0 = sp[0] * inv_sqrt_d;
            float s1 = sp[1] * inv_sqrt_d;
            float s2 = sp[2] * inv_sqrt_d;
            float s3 = sp[3] * inv_sqrt_d;
            float mx = fmaxf(fmaxf(s0, s1), fmaxf(s2, s3));
            mx = fmaxf(mx, __shfl_xor_sync(0xffffffffu, mx, 1));
            float x0 = __expf(s0 - mx);
            float x1 = __expf(s1 - mx);
            float x2 = __expf(s2 - mx);
            float x3 = __expf(s3 - mx);
            float sm = (x0 + x1) + (x2 + x3);
            sm += __shfl_xor_sync(0xffffffffu, sm, 1);
            float inv = __fdividef(1.0f, sm);
            float* wp = &swt[e * 9 + hb];
            wp[0] = x0 * inv;
            wp[1] = x1 * inv;
            wp[2] = x2 * inv;
            wp[3] = x3 * inv;
        }
        __syncthreads();

        // ---- phase B: thread (eg, j): out[e][j] = dot(wgt[e], VWT[dst][j]) ----
        const int j = h;
        float4 a0[4], a1[4];
#pragma unroll
        for (int i = 0; i < 4; i++) {
            const float4* vp = (const float4*)(g_VWT + (size_t)dst[i] * HD + j * 8);
            a0[i] = vp[0]; a1[i] = vp[1];
        }
#pragma unroll
        for (int i = 0; i < 4; i++) {
            const float* wp = &swt[(ebase + i) * 9];
            float res = wp[0] * a0[i].x + wp[1] * a0[i].y
                      + wp[2] * a0[i].z + wp[3] * a0[i].w
                      + wp[4] * a1[i].x + wp[5] * a1[i].y
                      + wp[6] * a1[i].z + wp[7] * a1[i].w;
            atomicAdd(&g_sum[(size_t)src[i] * OUT_DIM + j], res);
        }
        if (j == 0) {
#pragma unroll
            for (int i = 0; i < 4; i++) atomicAdd(&g_cnt[src[i]], 1);
        }
    }
}

__global__ void finalize_kernel(float* __restrict__ out, const float* __restrict__ bo) {
    int i = blockIdx.x * blockDim.x + threadIdx.x;
    if (i < N_NODES * OUT_DIM) {
        int n = i >> 3, j = i & 7;
        int c = g_cnt[n];
        float r = 0.f;
        if (c > 0) r = g_sum[i] / (float)c + bo[j];
        out[i] = r;
    }
}

extern "C" void kernel_launch(void* const* d_in, const int* in_sizes, int n_in,
                              void* d_out, int out_size)
{
    const float* x  = (const float*)d_in[0];
    const float* ea = (const float*)d_in[1];
    const float* Wq = (const float*)d_in[2];
    const float* bq = (const float*)d_in[3];
    const float* Wk = (const float*)d_in[4];
    const float* bk = (const float*)d_in[5];
    const float* Wv = (const float*)d_in[6];
    const float* bv = (const float*)d_in[7];
    const float* We = (const float*)d_in[8];
    const float* be = (const float*)d_in[9];
    const float* Wo = (const float*)d_in[10];
    const float* bo = (const float*)d_in[11];
    const void*  ei = d_in[12];
    float* out = (float*)d_out;

    zero_kernel<<<(N_NODES * OUT_DIM + 255) / 256, 256>>>();
    detect_kernel<<<1, 32>>>(ei);
    proj_kernel<<<dim3((N_NODES + 127) / 128, 3), 128>>>(
        x, Wq, bq, Wk, bk, Wv, bv, Wo);
    edge_kernel<<<1184, 128>>>(ea, We, be, ei);
    finalize_kernel<<<(N_NODES * OUT_DIM + 255) / 256, 256>>>(out, bo);
}